// round 1
// baseline (speedup 1.0000x reference)
#include <cuda_runtime.h>
#include <math.h>

#define Bz 64
#define Tz 400
#define Hz 256
#define Ez 128
#define Vz 50000
#define Xz 500
#define VXz 50500

// ---------------- device scratch (static, no allocation) ----------------
__device__ __align__(256) float gEmb[Bz * Ez];
__device__ __align__(256) float gX[Bz * Ez];
__device__ __align__(256) float gGates[Bz * 4 * Hz];
__device__ __align__(256) float gHs[Bz * Hz];
__device__ __align__(256) float gCs[Bz * Hz];
__device__ __align__(256) float gDecFea[Bz * 2 * Hz];
__device__ __align__(256) float gScores[Bz * Tz];
__device__ __align__(256) float gAttn[Bz * Tz];
__device__ __align__(256) float gCtPart[4][Bz * 2 * Hz];
__device__ __align__(256) float gCt[Bz * 2 * Hz];
__device__ __align__(256) float gPgen[Bz];
__device__ __align__(256) float gOut1[Bz * Hz];
__device__ __align__(256) float gLogits[(size_t)Bz * Vz];
__device__ __align__(256) float gRowMax[Bz];
__device__ __align__(256) float gScale[Bz];   // p_gen / sum(exp)

// ---------------- kernels ----------------

// gather embedding rows for y_t_1
__global__ void k_prep(const int* __restrict__ y, const float* __restrict__ emb) {
    int i = blockIdx.x * blockDim.x + threadIdx.x;
    if (i < Bz * Ez) {
        int b = i >> 7, e = i & 127;
        gEmb[i] = emb[(size_t)y[b] * Ez + e];
    }
}

// Generic small GEMM: C[b][n] = bias0[n](+bias1[n]) + sum_k A[b][k] * W[n][k]
// A is two concatenated segments (A0: len l0, A1: len l1), W rows likewise
// addressed via (W0, ws0) for k<l0 and (W1, ws1) for k>=l0.
// Requires (l0+l1) % 128 == 0 and N % 16 == 0. Grid.x = N/16, 256 threads.
__global__ void k_small_gemm(const float* __restrict__ A0, int l0,
                             const float* __restrict__ A1, int l1,
                             const float* __restrict__ W0, int ws0,
                             const float* __restrict__ W1, int ws1,
                             const float* __restrict__ bias0,
                             const float* __restrict__ bias1,
                             float* __restrict__ C, int N) {
    __shared__ float sA[128 * 65];
    __shared__ float sW[16 * 128];
    int tid = threadIdx.x;
    int b = tid & 63, ng = tid >> 6;
    int n0 = blockIdx.x * 16;
    int KD = l0 + l1;
    float acc[4];
#pragma unroll
    for (int i = 0; i < 4; i++) {
        int n = n0 + ng + 4 * i;
        acc[i] = bias0[n] + (bias1 ? bias1[n] : 0.f);
    }
    for (int k0 = 0; k0 < KD; k0 += 128) {
        __syncthreads();
        for (int idx = tid; idx < 64 * 128; idx += 256) {
            int bb = idx >> 7, k = idx & 127, kg = k0 + k;
            float v = (kg < l0) ? A0[bb * l0 + kg] : A1[bb * l1 + (kg - l0)];
            sA[k * 65 + bb] = v;
        }
        for (int idx = tid; idx < 16 * 128; idx += 256) {
            int r = idx >> 7, k = idx & 127, kg = k0 + k;
            float w = (kg < l0) ? W0[(size_t)(n0 + r) * ws0 + kg]
                                : W1[(size_t)(n0 + r) * ws1 + (kg - l0)];
            sW[r * 128 + k] = w;
        }
        __syncthreads();
#pragma unroll 8
        for (int k = 0; k < 128; k++) {
            float a = sA[k * 65 + b];
#pragma unroll
            for (int i = 0; i < 4; i++)
                acc[i] += a * sW[(ng + 4 * i) * 128 + k];
        }
    }
#pragma unroll
    for (int i = 0; i < 4; i++)
        C[(size_t)b * N + n0 + ng + 4 * i] = acc[i];
}

__device__ __forceinline__ float sigm(float x) { return 1.f / (1.f + expf(-x)); }

// LSTM cell elementwise. grid 64, 256 threads
__global__ void k_lstm(const float* __restrict__ c0) {
    int b = blockIdx.x, n = threadIdx.x;
    const float* g = gGates + b * 1024;
    float gi = g[n], gf = g[256 + n], gg = g[512 + n], go = g[768 + n];
    float cs = sigm(gf) * c0[b * 256 + n] + sigm(gi) * tanhf(gg);
    float hs = sigm(go) * tanhf(cs);
    gHs[b * 256 + n] = hs;
    gCs[b * 256 + n] = cs;
}

// attention scores: warp per (b,t). scores = sum_n Wv[n]*tanh(ef+decfea)
__global__ void k_scores(const float* __restrict__ ef, const float* __restrict__ Wv) {
    int gw = (int)((blockIdx.x * blockDim.x + threadIdx.x) >> 5);
    int lane = threadIdx.x & 31;
    if (gw >= Bz * Tz) return;
    int b = gw / Tz;
    const float4* e4 = (const float4*)(ef + (size_t)gw * 512);
    const float4* d4 = (const float4*)(gDecFea + b * 512);
    const float4* w4 = (const float4*)Wv;
    float acc = 0.f;
#pragma unroll
    for (int j = 0; j < 4; j++) {
        int idx = lane + 32 * j;
        float4 e = e4[idx], d = d4[idx], w = w4[idx];
        acc += w.x * tanhf(e.x + d.x) + w.y * tanhf(e.y + d.y)
             + w.z * tanhf(e.z + d.z) + w.w * tanhf(e.w + d.w);
    }
#pragma unroll
    for (int o = 16; o > 0; o >>= 1) acc += __shfl_xor_sync(0xffffffffu, acc, o);
    if (lane == 0) gScores[gw] = acc;
}

// softmax over T, mask, renorm, + stmt*mask. grid 64, 256 threads
__global__ void k_softmaxT(const float* __restrict__ mask, const float* __restrict__ stmt) {
    int b = blockIdx.x, tid = threadIdx.x;
    __shared__ float red[256];
    __shared__ float bc[2];
    float m = -1e30f;
    for (int t = tid; t < Tz; t += 256) m = fmaxf(m, gScores[b * Tz + t]);
    red[tid] = m;
    __syncthreads();
    for (int s = 128; s > 0; s >>= 1) {
        if (tid < s) red[tid] = fmaxf(red[tid], red[tid + s]);
        __syncthreads();
    }
    if (tid == 0) bc[0] = red[0];
    __syncthreads();
    m = bc[0];
    float s = 0.f;
    for (int t = tid; t < Tz; t += 256)
        s += expf(gScores[b * Tz + t] - m) * mask[b * Tz + t];
    red[tid] = s;
    __syncthreads();
    for (int s2 = 128; s2 > 0; s2 >>= 1) {
        if (tid < s2) red[tid] += red[tid + s2];
        __syncthreads();
    }
    if (tid == 0) bc[1] = red[0];
    __syncthreads();
    float inv = 1.f / bc[1];
    for (int t = tid; t < Tz; t += 256) {
        float pm = expf(gScores[b * Tz + t] - m) * mask[b * Tz + t];
        gAttn[b * Tz + t] = pm * inv + stmt[b * Tz + t] * mask[b * Tz + t];
    }
}

// context partials: grid (64, 4), 512 threads. chunk of 100 timesteps
__global__ void k_ctx(const float* __restrict__ enc) {
    int b = blockIdx.x, ch = blockIdx.y, n = threadIdx.x;
    int t0 = ch * 100;
    float acc = 0.f;
#pragma unroll 4
    for (int t = 0; t < 100; t++) {
        float a = gAttn[b * Tz + t0 + t];
        acc += a * enc[((size_t)b * Tz + t0 + t) * 512 + n];
    }
    gCtPart[ch][b * 512 + n] = acc;
}

// reduce context partials + p_gen. grid 64, 512 threads
__global__ void k_pgen(const float* __restrict__ Wpg, const float* __restrict__ bpg) {
    int b = blockIdx.x, n = threadIdx.x;
    __shared__ float red[512];
    float ct = gCtPart[0][b * 512 + n] + gCtPart[1][b * 512 + n]
             + gCtPart[2][b * 512 + n] + gCtPart[3][b * 512 + n];
    gCt[b * 512 + n] = ct;
    float p = Wpg[n] * ct;
    if (n < 256) p += Wpg[512 + n] * gHs[b * 256 + n] + Wpg[768 + n] * gCs[b * 256 + n];
    if (n < 128) p += Wpg[1024 + n] * gX[b * 128 + n];
    red[n] = p;
    __syncthreads();
    for (int s = 256; s > 0; s >>= 1) {
        if (n < s) red[n] += red[n + s];
        __syncthreads();
    }
    if (n == 0) gPgen[b] = 1.f / (1.f + expf(-(red[0] + bpg[0])));
}

// vocab GEMM: logits[b][v] = out1[b] . Wo2[v] + bo2[v]. 64 v-rows per block.
__global__ void k_logits(const float* __restrict__ Wo2, const float* __restrict__ bo2) {
    __shared__ float sA[64 * 68];
    __shared__ float sW[64 * 68];
    int tid = threadIdx.x;
    int tx = tid & 15, ty = tid >> 4;
    int v0 = blockIdx.x * 64;
    float acc[4][4];
#pragma unroll
    for (int i = 0; i < 4; i++)
#pragma unroll
        for (int j = 0; j < 4; j++) acc[i][j] = 0.f;

    for (int k0 = 0; k0 < 256; k0 += 64) {
        __syncthreads();
        for (int idx = tid; idx < 4096; idx += 256) {
            int bb = idx >> 6, k = idx & 63;
            sA[k * 68 + bb] = gOut1[bb * 256 + k0 + k];
        }
        for (int idx = tid; idx < 4096; idx += 256) {
            int v = idx >> 6, k = idx & 63;
            int vg = v0 + v;
            sW[k * 68 + v] = (vg < Vz) ? Wo2[(size_t)vg * 256 + k0 + k] : 0.f;
        }
        __syncthreads();
#pragma unroll 4
        for (int k = 0; k < 64; k++) {
            float4 a = *(const float4*)&sA[k * 68 + tx * 4];
            float4 w = *(const float4*)&sW[k * 68 + ty * 4];
            acc[0][0] += a.x * w.x; acc[0][1] += a.x * w.y; acc[0][2] += a.x * w.z; acc[0][3] += a.x * w.w;
            acc[1][0] += a.y * w.x; acc[1][1] += a.y * w.y; acc[1][2] += a.y * w.z; acc[1][3] += a.y * w.w;
            acc[2][0] += a.z * w.x; acc[2][1] += a.z * w.y; acc[2][2] += a.z * w.z; acc[2][3] += a.z * w.w;
            acc[3][0] += a.w * w.x; acc[3][1] += a.w * w.y; acc[3][2] += a.w * w.z; acc[3][3] += a.w * w.w;
        }
    }
#pragma unroll
    for (int i = 0; i < 4; i++) {
        int b = tx * 4 + i;
        int vbase = v0 + ty * 4;
        if (vbase + 3 < Vz) {
            float4 r;
            r.x = acc[i][0] + bo2[vbase + 0];
            r.y = acc[i][1] + bo2[vbase + 1];
            r.z = acc[i][2] + bo2[vbase + 2];
            r.w = acc[i][3] + bo2[vbase + 3];
            *(float4*)&gLogits[(size_t)b * Vz + vbase] = r;
        } else {
#pragma unroll
            for (int j = 0; j < 4; j++) {
                int v = vbase + j;
                if (v < Vz) gLogits[(size_t)b * Vz + v] = acc[i][j] + bo2[v];
            }
        }
    }
}

// per-row max & sum(exp) over V; store scale = p_gen/sum. grid 64, 512 threads
__global__ void k_rowred() {
    int b = blockIdx.x, tid = threadIdx.x;
    __shared__ float red[512];
    __shared__ float bm;
    const float* row = gLogits + (size_t)b * Vz;
    float m = -1e30f;
    for (int v = tid; v < Vz; v += 512) m = fmaxf(m, row[v]);
    red[tid] = m;
    __syncthreads();
    for (int s = 256; s > 0; s >>= 1) {
        if (tid < s) red[tid] = fmaxf(red[tid], red[tid + s]);
        __syncthreads();
    }
    if (tid == 0) bm = red[0];
    __syncthreads();
    float mm = bm;
    float s = 0.f;
    for (int v = tid; v < Vz; v += 512) s += expf(row[v] - mm);
    red[tid] = s;
    __syncthreads();
    for (int s2 = 256; s2 > 0; s2 >>= 1) {
        if (tid < s2) red[tid] += red[tid + s2];
        __syncthreads();
    }
    if (tid == 0) {
        gRowMax[b] = mm;
        gScale[b] = gPgen[b] / red[0];
    }
}

// final_dist + extra_zeros + pack small outputs
__global__ void k_final(float* __restrict__ out, const float* __restrict__ coverage,
                        int writeAll) {
    long long idx = (long long)blockIdx.x * 256 + threadIdx.x;
    const long long MAIN = (long long)Bz * VXz;
    if (idx < MAIN) {
        int b = (int)(idx / VXz);
        int v = (int)(idx - (long long)b * VXz);
        float r = 0.f;
        if (v < Vz)
            r = expf(gLogits[(size_t)b * Vz + v] - gRowMax[b]) * gScale[b];
        out[idx] = r;
    } else if (writeAll) {
        long long j = idx - MAIN;
        float r;
        if (j < 16384) r = gHs[j];
        else if ((j -= 16384) < 16384) r = gCs[j];
        else if ((j -= 16384) < 32768) r = gCt[j];
        else if ((j -= 32768) < 25600) r = gAttn[j];
        else if ((j -= 25600) < 64) r = gPgen[j];
        else if ((j -= 64) < 25600) r = coverage[j];
        else return;
        out[idx] = r;
    }
}

// scatter-add attention distribution into final_dist
__global__ void k_scatter(float* __restrict__ out, const int* __restrict__ ebev) {
    int i = blockIdx.x * 256 + threadIdx.x;
    if (i >= Bz * Tz) return;
    int b = i / Tz;
    float val = (1.f - gPgen[b]) * gAttn[i];
    atomicAdd(&out[(size_t)b * VXz + ebev[i]], val);
}

// ---------------- launcher ----------------
extern "C" void kernel_launch(void* const* d_in, const int* in_sizes, int n_in,
                              void* d_out, int out_size) {
    const int*   y    = (const int*)d_in[0];
    const float* h0   = (const float*)d_in[1];
    const float* c0   = (const float*)d_in[2];
    const float* enc  = (const float*)d_in[3];
    const float* ef   = (const float*)d_in[4];
    const float* stmt = (const float*)d_in[5];
    const float* mask = (const float*)d_in[6];
    const float* ct1  = (const float*)d_in[7];
    const int*   ebev = (const int*)d_in[9];
    const float* cov  = (const float*)d_in[10];
    int base = (n_in >= 28) ? 12 : 11;  // handle optional 'step' scalar
    const float* emb  = (const float*)d_in[base + 0];
    const float* Wxc  = (const float*)d_in[base + 1];
    const float* bxc  = (const float*)d_in[base + 2];
    const float* W_ih = (const float*)d_in[base + 3];
    const float* W_hh = (const float*)d_in[base + 4];
    const float* b_ih = (const float*)d_in[base + 5];
    const float* b_hh = (const float*)d_in[base + 6];
    const float* Wdp  = (const float*)d_in[base + 7];
    const float* bdp  = (const float*)d_in[base + 8];
    const float* Wv   = (const float*)d_in[base + 9];
    const float* Wpg  = (const float*)d_in[base + 10];
    const float* bpg  = (const float*)d_in[base + 11];
    const float* Wo1  = (const float*)d_in[base + 12];
    const float* bo1  = (const float*)d_in[base + 13];
    const float* Wo2  = (const float*)d_in[base + 14];
    const float* bo2  = (const float*)d_in[base + 15];
    float* out = (float*)d_out;

    float* pX; cudaGetSymbolAddress((void**)&pX, gX);
    float* pG; cudaGetSymbolAddress((void**)&pG, gGates);
    float* pD; cudaGetSymbolAddress((void**)&pD, gDecFea);
    float* pE; cudaGetSymbolAddress((void**)&pE, gEmb);
    float* pHs; cudaGetSymbolAddress((void**)&pHs, gHs);
    float* pCs; cudaGetSymbolAddress((void**)&pCs, gCs);
    float* pCt; cudaGetSymbolAddress((void**)&pCt, gCt);
    float* pO1; cudaGetSymbolAddress((void**)&pO1, gOut1);

    // 1) embedding gather
    k_prep<<<(Bz * Ez + 255) / 256, 256>>>(y, emb);
    // 2) x = [c_t_1, y_emb] @ Wxc^T + bxc   (KD=640, N=128)
    k_small_gemm<<<128 / 16, 256>>>(ct1, 512, pE, 128,
                                    Wxc, 640, Wxc + 512, 640,
                                    bxc, nullptr, pX, 128);
    // 3) gates = [x, h0] @ [W_ih|W_hh]^T + b_ih + b_hh  (KD=384, N=1024)
    k_small_gemm<<<1024 / 16, 256>>>(pX, 128, h0, 256,
                                     W_ih, 128, W_hh, 256,
                                     b_ih, b_hh, pG, 1024);
    // 4) LSTM nonlinearity
    k_lstm<<<Bz, 256>>>(c0);
    // 5) dec_fea = [h_s, c_s] @ Wdp^T + bdp  (KD=512, N=512)
    k_small_gemm<<<512 / 16, 256>>>(pHs, 256, pCs, 256,
                                    Wdp, 512, Wdp + 256, 512,
                                    bdp, nullptr, pD, 512);
    // 6) attention scores (warp per (b,t))
    k_scores<<<(Bz * Tz) / 8, 256>>>(ef, Wv);
    // 7) softmax over T + mask renorm + stmt
    k_softmaxT<<<Bz, 256>>>(mask, stmt);
    // 8) context partials
    k_ctx<<<dim3(Bz, 4), 512>>>(enc);
    // 9) context reduce + p_gen
    k_pgen<<<Bz, 512>>>(Wpg, bpg);
    // 10) output = [h_s, c_t] @ Wo1^T + bo1  (KD=768, N=256)
    k_small_gemm<<<256 / 16, 256>>>(pHs, 256, pCt, 512,
                                    Wo1, 768, Wo1 + 256, 768,
                                    bo1, nullptr, pO1, 256);
    // 11) vocab logits GEMM
    k_logits<<<(Vz + 63) / 64, 256>>>(Wo2, bo2);
    // 12) row max + sum(exp), fold p_gen
    k_rowred<<<Bz, 512>>>();
    // 13) final dist + extra zeros + pack other outputs
    const long long MAIN = (long long)Bz * VXz;           // 3,232,000
    const long long ALL  = MAIN + 16384 + 16384 + 32768 + 25600 + 64 + 25600;
    int writeAll = ((long long)out_size >= ALL) ? 1 : 0;
    long long tot = writeAll ? ALL : MAIN;
    k_final<<<(unsigned)((tot + 255) / 256), 256>>>(out, cov, writeAll);
    // 14) scatter-add copy distribution
    k_scatter<<<(Bz * Tz + 255) / 256, 256>>>(out, ebev);
}

// round 2
// speedup vs baseline: 1.1155x; 1.1155x over previous
#include <cuda_runtime.h>
#include <math.h>

#define Bz 64
#define Tz 400
#define Hz 256
#define Ez 128
#define Vz 50000
#define Xz 500
#define VXz 50500

// ---------------- device scratch (static, no allocation) ----------------
__device__ __align__(256) float gX[Bz * Ez];
__device__ __align__(256) float gGates[Bz * 4 * Hz];
__device__ __align__(256) float gHs[Bz * Hz];
__device__ __align__(256) float gCs[Bz * Hz];
__device__ __align__(256) float gDecFea[Bz * 2 * Hz];
__device__ __align__(256) float gScores[Bz * Tz];
__device__ __align__(256) float gAttn[Bz * Tz];
__device__ __align__(256) float gCtPart[4][Bz * 2 * Hz];
__device__ __align__(256) float gCt[Bz * 2 * Hz];
__device__ __align__(256) float gPgen[Bz];
__device__ __align__(256) float gOut1[Bz * Hz];
__device__ __align__(256) float gOut1T[Hz * Bz];     // [k][b] transposed copy
__device__ __align__(256) float gLogits[(size_t)Bz * Vz];
__device__ __align__(256) float gRowMax[Bz];
__device__ __align__(256) float gScale[Bz];   // p_gen / sum(exp)

// ---------------- f32x2 helpers (Blackwell packed fp32) ----------------
__device__ __forceinline__ unsigned long long pack2(float lo, float hi) {
    unsigned long long r;
    asm("mov.b64 %0, {%1, %2};" : "=l"(r) : "f"(lo), "f"(hi));
    return r;
}
__device__ __forceinline__ void fma2(unsigned long long& acc, unsigned long long a,
                                     unsigned long long b) {
    asm("fma.rn.f32x2 %0, %1, %2, %0;" : "+l"(acc) : "l"(a), "l"(b));
}
__device__ __forceinline__ float2 unpk2(unsigned long long v) {
    float2 r;
    asm("mov.b64 {%0, %1}, %2;" : "=f"(r.x), "=f"(r.y) : "l"(v));
    return r;
}

// ---------------- kernels ----------------

// Generic small GEMM: C[b][n] = bias0[n](+bias1[n]) + sum_k A[b][k] * W[n][k]
// A is two concatenated segments (A0 len l0; A1 len l1, optionally row-gathered
// by 'gather'). W rows via (W0, ws0) k<l0 and (W1, ws1) k>=l0.
// Optionally also writes CT[n*64+b]. (l0+l1)%128==0, N%16==0. grid N/16, 256 thr.
__global__ void k_small_gemm(const float* __restrict__ A0, int l0,
                             const float* __restrict__ A1, int l1,
                             const int* __restrict__ gather,
                             const float* __restrict__ W0, int ws0,
                             const float* __restrict__ W1, int ws1,
                             const float* __restrict__ bias0,
                             const float* __restrict__ bias1,
                             float* __restrict__ C, float* __restrict__ CT, int N) {
    __shared__ float sA[128 * 65];
    __shared__ float sW[16 * 128];
    int tid = threadIdx.x;
    int b = tid & 63, ng = tid >> 6;
    int n0 = blockIdx.x * 16;
    int KD = l0 + l1;
    float acc[4];
#pragma unroll
    for (int i = 0; i < 4; i++) {
        int n = n0 + ng + 4 * i;
        acc[i] = bias0[n] + (bias1 ? bias1[n] : 0.f);
    }
    for (int k0 = 0; k0 < KD; k0 += 128) {
        __syncthreads();
        for (int idx = tid; idx < 64 * 128; idx += 256) {
            int bb = idx >> 7, k = idx & 127, kg = k0 + k;
            float v;
            if (kg < l0) v = A0[bb * l0 + kg];
            else {
                int row = gather ? gather[bb] : bb;
                v = A1[(size_t)row * l1 + (kg - l0)];
            }
            sA[k * 65 + bb] = v;
        }
        for (int idx = tid; idx < 16 * 128; idx += 256) {
            int r = idx >> 7, k = idx & 127, kg = k0 + k;
            float w = (kg < l0) ? W0[(size_t)(n0 + r) * ws0 + kg]
                                : W1[(size_t)(n0 + r) * ws1 + (kg - l0)];
            sW[r * 128 + k] = w;
        }
        __syncthreads();
#pragma unroll 8
        for (int k = 0; k < 128; k++) {
            float a = sA[k * 65 + b];
#pragma unroll
            for (int i = 0; i < 4; i++)
                acc[i] += a * sW[(ng + 4 * i) * 128 + k];
        }
    }
#pragma unroll
    for (int i = 0; i < 4; i++) {
        int n = n0 + ng + 4 * i;
        C[(size_t)b * N + n] = acc[i];
        if (CT) CT[n * 64 + b] = acc[i];
    }
}

__device__ __forceinline__ float sigm(float x) { return 1.f / (1.f + expf(-x)); }

// LSTM cell elementwise. grid 64, 256 threads
__global__ void k_lstm(const float* __restrict__ c0) {
    int b = blockIdx.x, n = threadIdx.x;
    const float* g = gGates + b * 1024;
    float gi = g[n], gf = g[256 + n], gg = g[512 + n], go = g[768 + n];
    float cs = sigm(gf) * c0[b * 256 + n] + sigm(gi) * tanhf(gg);
    float hs = sigm(go) * tanhf(cs);
    gHs[b * 256 + n] = hs;
    gCs[b * 256 + n] = cs;
}

// attention scores: warp per (b,t). scores = sum_n Wv[n]*tanh(ef+decfea)
__global__ void k_scores(const float* __restrict__ ef, const float* __restrict__ Wv) {
    int gw = (int)((blockIdx.x * blockDim.x + threadIdx.x) >> 5);
    int lane = threadIdx.x & 31;
    if (gw >= Bz * Tz) return;
    int b = gw / Tz;
    const float4* e4 = (const float4*)(ef + (size_t)gw * 512);
    const float4* d4 = (const float4*)(gDecFea + b * 512);
    const float4* w4 = (const float4*)Wv;
    float acc = 0.f;
#pragma unroll
    for (int j = 0; j < 4; j++) {
        int idx = lane + 32 * j;
        float4 e = e4[idx], d = d4[idx], w = w4[idx];
        acc += w.x * tanhf(e.x + d.x) + w.y * tanhf(e.y + d.y)
             + w.z * tanhf(e.z + d.z) + w.w * tanhf(e.w + d.w);
    }
#pragma unroll
    for (int o = 16; o > 0; o >>= 1) acc += __shfl_xor_sync(0xffffffffu, acc, o);
    if (lane == 0) gScores[gw] = acc;
}

// softmax over T, mask, renorm, + stmt*mask. grid 64, 256 threads
__global__ void k_softmaxT(const float* __restrict__ mask, const float* __restrict__ stmt) {
    int b = blockIdx.x, tid = threadIdx.x;
    __shared__ float red[256];
    __shared__ float bc[2];
    float m = -1e30f;
    for (int t = tid; t < Tz; t += 256) m = fmaxf(m, gScores[b * Tz + t]);
    red[tid] = m;
    __syncthreads();
    for (int s = 128; s > 0; s >>= 1) {
        if (tid < s) red[tid] = fmaxf(red[tid], red[tid + s]);
        __syncthreads();
    }
    if (tid == 0) bc[0] = red[0];
    __syncthreads();
    m = bc[0];
    float s = 0.f;
    for (int t = tid; t < Tz; t += 256)
        s += expf(gScores[b * Tz + t] - m) * mask[b * Tz + t];
    red[tid] = s;
    __syncthreads();
    for (int s2 = 128; s2 > 0; s2 >>= 1) {
        if (tid < s2) red[tid] += red[tid + s2];
        __syncthreads();
    }
    if (tid == 0) bc[1] = red[0];
    __syncthreads();
    float inv = 1.f / bc[1];
    for (int t = tid; t < Tz; t += 256) {
        float pm = expf(gScores[b * Tz + t] - m) * mask[b * Tz + t];
        gAttn[b * Tz + t] = pm * inv + stmt[b * Tz + t] * mask[b * Tz + t];
    }
}

// context partials: grid (64, 4), 512 threads. chunk of 100 timesteps
__global__ void k_ctx(const float* __restrict__ enc) {
    int b = blockIdx.x, ch = blockIdx.y, n = threadIdx.x;
    int t0 = ch * 100;
    float acc = 0.f;
#pragma unroll 4
    for (int t = 0; t < 100; t++) {
        float a = gAttn[b * Tz + t0 + t];
        acc += a * enc[((size_t)b * Tz + t0 + t) * 512 + n];
    }
    gCtPart[ch][b * 512 + n] = acc;
}

// reduce context partials + p_gen. grid 64, 512 threads
__global__ void k_pgen(const float* __restrict__ Wpg, const float* __restrict__ bpg) {
    int b = blockIdx.x, n = threadIdx.x;
    __shared__ float red[512];
    float ct = gCtPart[0][b * 512 + n] + gCtPart[1][b * 512 + n]
             + gCtPart[2][b * 512 + n] + gCtPart[3][b * 512 + n];
    gCt[b * 512 + n] = ct;
    float p = Wpg[n] * ct;
    if (n < 256) p += Wpg[512 + n] * gHs[b * 256 + n] + Wpg[768 + n] * gCs[b * 256 + n];
    if (n < 128) p += Wpg[1024 + n] * gX[b * 128 + n];
    red[n] = p;
    __syncthreads();
    for (int s = 256; s > 0; s >>= 1) {
        if (n < s) red[n] += red[n + s];
        __syncthreads();
    }
    if (n == 0) gPgen[b] = 1.f / (1.f + expf(-(red[0] + bpg[0])));
}

// ---------------- vocab GEMM: 128 v x 64 b per block, f32x2 FMA ----------------
#define LOG_NV 128
#define LOG_KT 32
__global__ void __launch_bounds__(128) k_logits(const float* __restrict__ Wo2,
                                                const float* __restrict__ bo2) {
    __shared__ float sA[LOG_KT * 64];        // [k][b]
    __shared__ float sW[LOG_KT * LOG_NV];    // [k][v ^ ((k>>2)*4)]
    int tid = threadIdx.x;
    int tx = tid & 7;        // batch octet: {tx*4..+3} U {32+tx*4..+3}
    int ty = tid >> 3;       // 0..15 -> 8 vocab each
    int v0 = ty * 8;
    int vb = blockIdx.x * LOG_NV;

    unsigned long long acc[4][8];
#pragma unroll
    for (int p = 0; p < 4; p++)
#pragma unroll
        for (int j = 0; j < 8; j++) acc[p][j] = 0ULL;

    for (int k0 = 0; k0 < 256; k0 += LOG_KT) {
        __syncthreads();
        // A tile from pre-transposed gOut1T: 32k x 64b = 512 float4
#pragma unroll
        for (int r = 0; r < 4; r++) {
            int fid = r * 128 + tid;
            int k = fid >> 4, bq = fid & 15;
            float4 v = *(const float4*)&gOut1T[(k0 + k) * 64 + bq * 4];
            *(float4*)&sA[k * 64 + bq * 4] = v;
        }
        // W tile: 128v x 32k = 1024 float4, XOR-swizzled store (conflict-free)
#pragma unroll
        for (int r = 0; r < 8; r++) {
            int fid = r * 128 + tid;
            int v = fid >> 3, kq = fid & 7;
            int vg = vb + v;
            float4 w = (vg < Vz) ? *(const float4*)&Wo2[(size_t)vg * 256 + k0 + kq * 4]
                                 : make_float4(0.f, 0.f, 0.f, 0.f);
            int sv = v ^ (kq * 4);
            sW[(kq * 4 + 0) * LOG_NV + sv] = w.x;
            sW[(kq * 4 + 1) * LOG_NV + sv] = w.y;
            sW[(kq * 4 + 2) * LOG_NV + sv] = w.z;
            sW[(kq * 4 + 3) * LOG_NV + sv] = w.w;
        }
        __syncthreads();
#pragma unroll
        for (int k = 0; k < LOG_KT; k++) {
            float4 aA = *(const float4*)&sA[k * 64 + tx * 4];
            float4 aB = *(const float4*)&sA[k * 64 + 32 + tx * 4];
            int s = (k >> 2) * 4;
            const float* wr = &sW[k * LOG_NV];
            float4 w0 = *(const float4*)&wr[v0 ^ s];
            float4 w1 = *(const float4*)&wr[(v0 + 4) ^ s];
            unsigned long long ap0 = pack2(aA.x, aA.y);
            unsigned long long ap1 = pack2(aA.z, aA.w);
            unsigned long long ap2 = pack2(aB.x, aB.y);
            unsigned long long ap3 = pack2(aB.z, aB.w);
            float wv[8] = {w0.x, w0.y, w0.z, w0.w, w1.x, w1.y, w1.z, w1.w};
#pragma unroll
            for (int j = 0; j < 8; j++) {
                unsigned long long wd = pack2(wv[j], wv[j]);
                fma2(acc[0][j], ap0, wd);
                fma2(acc[1][j], ap1, wd);
                fma2(acc[2][j], ap2, wd);
                fma2(acc[3][j], ap3, wd);
            }
        }
    }
    // epilogue: 8 batches x 8 v per thread, float4 stores
    int vg0 = vb + v0;
    if (vg0 + 7 < Vz) {
        float4 bi0 = *(const float4*)&bo2[vg0];
        float4 bi1 = *(const float4*)&bo2[vg0 + 4];
#pragma unroll
        for (int p = 0; p < 4; p++) {
            float2 u0 = unpk2(acc[p][0]), u1 = unpk2(acc[p][1]);
            float2 u2 = unpk2(acc[p][2]), u3 = unpk2(acc[p][3]);
            float2 u4 = unpk2(acc[p][4]), u5 = unpk2(acc[p][5]);
            float2 u6 = unpk2(acc[p][6]), u7 = unpk2(acc[p][7]);
            int bLo = (p >> 1) * 32 + tx * 4 + (p & 1) * 2;
            float4 lo0 = make_float4(u0.x + bi0.x, u1.x + bi0.y, u2.x + bi0.z, u3.x + bi0.w);
            float4 lo1 = make_float4(u4.x + bi1.x, u5.x + bi1.y, u6.x + bi1.z, u7.x + bi1.w);
            float4 hi0 = make_float4(u0.y + bi0.x, u1.y + bi0.y, u2.y + bi0.z, u3.y + bi0.w);
            float4 hi1 = make_float4(u4.y + bi1.x, u5.y + bi1.y, u6.y + bi1.z, u7.y + bi1.w);
            *(float4*)&gLogits[(size_t)bLo * Vz + vg0] = lo0;
            *(float4*)&gLogits[(size_t)bLo * Vz + vg0 + 4] = lo1;
            *(float4*)&gLogits[(size_t)(bLo + 1) * Vz + vg0] = hi0;
            *(float4*)&gLogits[(size_t)(bLo + 1) * Vz + vg0 + 4] = hi1;
        }
    }
}

// per-row max & sum(exp) over V; scale = p_gen/sum. grid 64, 512 threads
__global__ void k_rowred() {
    int b = blockIdx.x, tid = threadIdx.x;
    __shared__ float red[512];
    __shared__ float bm;
    const float4* row = (const float4*)(gLogits + (size_t)b * Vz);
    float m = -1e30f;
    for (int v = tid; v < Vz / 4; v += 512) {
        float4 x = row[v];
        m = fmaxf(m, fmaxf(fmaxf(x.x, x.y), fmaxf(x.z, x.w)));
    }
    red[tid] = m;
    __syncthreads();
    for (int s = 256; s > 0; s >>= 1) {
        if (tid < s) red[tid] = fmaxf(red[tid], red[tid + s]);
        __syncthreads();
    }
    if (tid == 0) bm = red[0];
    __syncthreads();
    float mm = bm;
    float s = 0.f;
    for (int v = tid; v < Vz / 4; v += 512) {
        float4 x = row[v];
        s += expf(x.x - mm) + expf(x.y - mm) + expf(x.z - mm) + expf(x.w - mm);
    }
    red[tid] = s;
    __syncthreads();
    for (int s2 = 256; s2 > 0; s2 >>= 1) {
        if (tid < s2) red[tid] += red[tid + s2];
        __syncthreads();
    }
    if (tid == 0) {
        gRowMax[b] = mm;
        gScale[b] = gPgen[b] / red[0];
    }
}

// final_dist (float4) + extra_zeros + pack small outputs
__global__ void k_final(float* __restrict__ out, const float* __restrict__ coverage,
                        int writeAll) {
    const int ROW4 = VXz / 4;                 // 12625
    long long idx = (long long)blockIdx.x * 256 + threadIdx.x;
    const long long MAIN4 = (long long)Bz * ROW4;
    if (idx < MAIN4) {
        int b = (int)(idx / ROW4);
        int v = (int)(idx - (long long)b * ROW4) * 4;
        float4 r = make_float4(0.f, 0.f, 0.f, 0.f);
        if (v < Vz) {
            float m = gRowMax[b], sc = gScale[b];
            float4 lg = *(const float4*)&gLogits[(size_t)b * Vz + v];
            r.x = expf(lg.x - m) * sc;
            r.y = expf(lg.y - m) * sc;
            r.z = expf(lg.z - m) * sc;
            r.w = expf(lg.w - m) * sc;
        }
        *(float4*)&out[(size_t)b * VXz + v] = r;
    } else if (writeAll) {
        long long j = idx - MAIN4;
        float r;
        long long base = (long long)Bz * VXz;
        if (j < 16384) r = gHs[j];
        else if ((j -= 16384) < 16384) r = gCs[j];
        else if ((j -= 16384) < 32768) r = gCt[j];
        else if ((j -= 32768) < 25600) r = gAttn[j];
        else if ((j -= 25600) < 64) r = gPgen[j];
        else if ((j -= 64) < 25600) r = coverage[j];
        else return;
        out[base + (idx - MAIN4)] = r;
    }
}

// scatter-add attention distribution into final_dist
__global__ void k_scatter(float* __restrict__ out, const int* __restrict__ ebev) {
    int i = blockIdx.x * 256 + threadIdx.x;
    if (i >= Bz * Tz) return;
    int b = i / Tz;
    float val = (1.f - gPgen[b]) * gAttn[i];
    atomicAdd(&out[(size_t)b * VXz + ebev[i]], val);
}

// ---------------- launcher ----------------
extern "C" void kernel_launch(void* const* d_in, const int* in_sizes, int n_in,
                              void* d_out, int out_size) {
    const int*   y    = (const int*)d_in[0];
    const float* h0   = (const float*)d_in[1];
    const float* c0   = (const float*)d_in[2];
    const float* enc  = (const float*)d_in[3];
    const float* ef   = (const float*)d_in[4];
    const float* stmt = (const float*)d_in[5];
    const float* mask = (const float*)d_in[6];
    const float* ct1  = (const float*)d_in[7];
    const int*   ebev = (const int*)d_in[9];
    const float* cov  = (const float*)d_in[10];
    int base = (n_in >= 28) ? 12 : 11;
    const float* emb  = (const float*)d_in[base + 0];
    const float* Wxc  = (const float*)d_in[base + 1];
    const float* bxc  = (const float*)d_in[base + 2];
    const float* W_ih = (const float*)d_in[base + 3];
    const float* W_hh = (const float*)d_in[base + 4];
    const float* b_ih = (const float*)d_in[base + 5];
    const float* b_hh = (const float*)d_in[base + 6];
    const float* Wdp  = (const float*)d_in[base + 7];
    const float* bdp  = (const float*)d_in[base + 8];
    const float* Wv   = (const float*)d_in[base + 9];
    const float* Wpg  = (const float*)d_in[base + 10];
    const float* bpg  = (const float*)d_in[base + 11];
    const float* Wo1  = (const float*)d_in[base + 12];
    const float* bo1  = (const float*)d_in[base + 13];
    const float* Wo2  = (const float*)d_in[base + 14];
    const float* bo2  = (const float*)d_in[base + 15];
    float* out = (float*)d_out;

    float* pX;  cudaGetSymbolAddress((void**)&pX, gX);
    float* pG;  cudaGetSymbolAddress((void**)&pG, gGates);
    float* pD;  cudaGetSymbolAddress((void**)&pD, gDecFea);
    float* pHs; cudaGetSymbolAddress((void**)&pHs, gHs);
    float* pCs; cudaGetSymbolAddress((void**)&pCs, gCs);
    float* pCt; cudaGetSymbolAddress((void**)&pCt, gCt);
    float* pO1; cudaGetSymbolAddress((void**)&pO1, gOut1);
    float* pO1T; cudaGetSymbolAddress((void**)&pO1T, gOut1T);

    // 1) x = [c_t_1, emb[y]] @ Wxc^T + bxc   (KD=640, N=128) — gather fused
    k_small_gemm<<<128 / 16, 256>>>(ct1, 512, emb, 128, y,
                                    Wxc, 640, Wxc + 512, 640,
                                    bxc, nullptr, pX, nullptr, 128);
    // 2) gates = [x, h0] @ [W_ih|W_hh]^T + b_ih + b_hh  (KD=384, N=1024)
    k_small_gemm<<<1024 / 16, 256>>>(pX, 128, h0, 256, nullptr,
                                     W_ih, 128, W_hh, 256,
                                     b_ih, b_hh, pG, nullptr, 1024);
    // 3) LSTM nonlinearity
    k_lstm<<<Bz, 256>>>(c0);
    // 4) dec_fea = [h_s, c_s] @ Wdp^T + bdp  (KD=512, N=512)
    k_small_gemm<<<512 / 16, 256>>>(pHs, 256, pCs, 256, nullptr,
                                    Wdp, 512, Wdp + 256, 512,
                                    bdp, nullptr, pD, nullptr, 512);
    // 5) attention scores
    k_scores<<<(Bz * Tz) / 8, 256>>>(ef, Wv);
    // 6) softmax over T + mask renorm + stmt
    k_softmaxT<<<Bz, 256>>>(mask, stmt);
    // 7) context partials
    k_ctx<<<dim3(Bz, 4), 512>>>(enc);
    // 8) context reduce + p_gen
    k_pgen<<<Bz, 512>>>(Wpg, bpg);
    // 9) output = [h_s, c_t] @ Wo1^T + bo1 — also writes transposed copy
    k_small_gemm<<<256 / 16, 256>>>(pHs, 256, pCt, 512, nullptr,
                                    Wo1, 768, Wo1 + 256, 768,
                                    bo1, nullptr, pO1, pO1T, 256);
    // 10) vocab logits GEMM (f32x2)
    k_logits<<<(Vz + LOG_NV - 1) / LOG_NV, 128>>>(Wo2, bo2);
    // 11) row max + sum(exp), fold p_gen
    k_rowred<<<Bz, 512>>>();
    // 12) final dist + extra zeros + pack other outputs
    const long long MAIN4 = (long long)Bz * (VXz / 4);     // 808,000 float4 slots
    const long long TAIL  = 16384 + 16384 + 32768 + 25600 + 64 + 25600;
    const long long ALL   = (long long)Bz * VXz + TAIL;
    int writeAll = ((long long)out_size >= ALL) ? 1 : 0;
    long long slots = MAIN4 + (writeAll ? TAIL : 0);
    k_final<<<(unsigned)((slots + 255) / 256), 256>>>(out, cov, writeAll);
    // 13) scatter-add copy distribution
    k_scatter<<<(Bz * Tz + 255) / 256, 256>>>(out, ebev);
}

// round 3
// speedup vs baseline: 1.5616x; 1.3999x over previous
#include <cuda_runtime.h>
#include <math.h>

#define Bz 64
#define Tz 400
#define Hz 256
#define Ez 128
#define Vz 50000
#define Xz 500
#define VXz 50500

// ---------------- device scratch (static, no allocation) ----------------
__device__ __align__(256) float gXPart[5][Bz * Ez];           // x partials
__device__ __align__(256) float gGatesPart[3][Bz * 4 * Hz];   // gate partials
__device__ __align__(256) float gDecPart[4][Bz * 2 * Hz];     // dec_fea partials
__device__ __align__(256) float gO1TPart[6][Hz * Bz];         // out1^T partials
__device__ __align__(256) float gHs[Bz * Hz];
__device__ __align__(256) float gCs[Bz * Hz];
__device__ __align__(256) float gScores[Bz * Tz];
__device__ __align__(256) float gAttn[Bz * Tz];
__device__ __align__(256) float gCtPart[4][Bz * 2 * Hz];
__device__ __align__(256) float gCt[Bz * 2 * Hz];
__device__ __align__(256) float gPgen[Bz];
__device__ __align__(256) float gLogits[(size_t)Bz * Vz];
__device__ __align__(256) float gRowMax[Bz];
__device__ __align__(256) float gScale[Bz];

// ---------------- f32x2 helpers ----------------
__device__ __forceinline__ unsigned long long pack2(float lo, float hi) {
    unsigned long long r;
    asm("mov.b64 %0, {%1, %2};" : "=l"(r) : "f"(lo), "f"(hi));
    return r;
}
__device__ __forceinline__ void fma2(unsigned long long& acc, unsigned long long a,
                                     unsigned long long b) {
    asm("fma.rn.f32x2 %0, %1, %2, %0;" : "+l"(acc) : "l"(a), "l"(b));
}
__device__ __forceinline__ float2 unpk2(unsigned long long v) {
    float2 r;
    asm("mov.b64 {%0, %1}, %2;" : "=f"(r.x), "=f"(r.y) : "l"(v));
    return r;
}

// ---------------- split-K small GEMM ----------------
// out[kc][b][n] (+optional transposed outT[kc][n][b]) partial products:
//   sum_{k in chunk kc} A[b][k] * W[n][k]
// A: segment0 = sum of p0 partials (stride ps0) + biasA0, len l0;
//    segment1 = A1 (optionally row-gathered), len l1. l0 % 128 == 0.
// W rows: (W0, ws0) for k < l0; (W1, ws1) for k >= l0.
// grid (N/16, KD/128), 256 threads.
__global__ void k_gemm(const float* __restrict__ A0, int l0, int p0, int ps0,
                       const float* __restrict__ biasA0,
                       const float* __restrict__ A1, int l1,
                       const int* __restrict__ gather,
                       const float* __restrict__ W0, int ws0,
                       const float* __restrict__ W1, int ws1,
                       float* __restrict__ outP, float* __restrict__ outTP, int N) {
    __shared__ float sA[128 * 65];   // [k][b]
    __shared__ float sW[128 * 20];   // [k][r], stride 20 (float4-aligned rows)
    int tid = threadIdx.x;
    int b = tid & 63, ng = tid >> 6;
    int n0 = blockIdx.x * 16;
    int k0 = blockIdx.y * 128;

    // A tile: 64 b x 128 k
    for (int idx = tid; idx < 64 * 128; idx += 256) {
        int bb = idx >> 7, k = idx & 127;
        int kg = k0 + k;
        float v;
        if (kg < l0) {
            v = biasA0 ? biasA0[kg] : 0.f;
            for (int p = 0; p < p0; p++) v += A0[p * ps0 + bb * l0 + kg];
        } else {
            int row = gather ? gather[bb] : bb;
            v = A1[(size_t)row * l1 + (kg - l0)];
        }
        sA[k * 65 + bb] = v;
    }
    // W tile: 16 n x 128 k -> sW[k][r] (conflict-free: r per lane)
    for (int idx = tid; idx < 512; idx += 256) {
        int r = idx & 15, kq = idx >> 4;
        int kg = k0 + kq * 4;
        float4 w = (kg < l0) ? *(const float4*)&W0[(size_t)(n0 + r) * ws0 + kg]
                             : *(const float4*)&W1[(size_t)(n0 + r) * ws1 + (kg - l0)];
        sW[(kq * 4 + 0) * 20 + r] = w.x;
        sW[(kq * 4 + 1) * 20 + r] = w.y;
        sW[(kq * 4 + 2) * 20 + r] = w.z;
        sW[(kq * 4 + 3) * 20 + r] = w.w;
    }
    __syncthreads();

    float acc[4] = {0.f, 0.f, 0.f, 0.f};
#pragma unroll 8
    for (int k = 0; k < 128; k++) {
        float a = sA[k * 65 + b];
        float4 w = *(const float4*)&sW[k * 20 + ng * 4];
        acc[0] += a * w.x; acc[1] += a * w.y; acc[2] += a * w.z; acc[3] += a * w.w;
    }
    int n = n0 + ng * 4;
    if (outP)
        *(float4*)&outP[(size_t)blockIdx.y * 64 * N + b * N + n] =
            make_float4(acc[0], acc[1], acc[2], acc[3]);
    if (outTP) {
        float* o = outTP + (size_t)blockIdx.y * N * 64;
#pragma unroll
        for (int i = 0; i < 4; i++) o[(n + i) * 64 + b] = acc[i];
    }
}

__device__ __forceinline__ float sigm(float x) { return 1.f / (1.f + expf(-x)); }

// LSTM cell: sum 3 gate partials + biases. grid 64, 256 threads
__global__ void k_lstm(const float* __restrict__ c0, const float* __restrict__ b_ih,
                       const float* __restrict__ b_hh) {
    int b = blockIdx.x, n = threadIdx.x;
    float gi = b_ih[n] + b_hh[n];
    float gf = b_ih[256 + n] + b_hh[256 + n];
    float gg = b_ih[512 + n] + b_hh[512 + n];
    float go = b_ih[768 + n] + b_hh[768 + n];
#pragma unroll
    for (int p = 0; p < 3; p++) {
        const float* g = gGatesPart[p] + b * 1024;
        gi += g[n]; gf += g[256 + n]; gg += g[512 + n]; go += g[768 + n];
    }
    float cs = sigm(gf) * c0[b * 256 + n] + sigm(gi) * tanhf(gg);
    float hs = sigm(go) * tanhf(cs);
    gHs[b * 256 + n] = hs;
    gCs[b * 256 + n] = cs;
}

// attention scores: block per (b, 8 t's). dec_fea partial-sum + Wv staged in smem.
__global__ void k_scores(const float* __restrict__ ef, const float* __restrict__ Wv,
                         const float* __restrict__ bdp) {
    __shared__ float sD[512], sV[512];
    int b = blockIdx.x / 50;
    int t0 = (blockIdx.x % 50) * 8;
    int tid = threadIdx.x;
    for (int i = tid; i < 512; i += 256) {
        float d = bdp[i];
#pragma unroll
        for (int p = 0; p < 4; p++) d += gDecPart[p][b * 512 + i];
        sD[i] = d;
        sV[i] = Wv[i];
    }
    __syncthreads();
    int w = tid >> 5, lane = tid & 31;
    int t = t0 + w;
    const float4* e4 = (const float4*)(ef + ((size_t)b * Tz + t) * 512);
    float acc = 0.f;
#pragma unroll
    for (int j = 0; j < 4; j++) {
        int idx = lane + 32 * j;
        float4 e = e4[idx];
        float4 d = *(const float4*)&sD[idx * 4];
        float4 v = *(const float4*)&sV[idx * 4];
        acc += v.x * tanhf(e.x + d.x) + v.y * tanhf(e.y + d.y)
             + v.z * tanhf(e.z + d.z) + v.w * tanhf(e.w + d.w);
    }
#pragma unroll
    for (int o = 16; o > 0; o >>= 1) acc += __shfl_xor_sync(0xffffffffu, acc, o);
    if (lane == 0) gScores[b * Tz + t] = acc;
}

// softmax over T, mask, renorm, + stmt*mask. grid 64, 256 threads
__global__ void k_softmaxT(const float* __restrict__ mask, const float* __restrict__ stmt) {
    int b = blockIdx.x, tid = threadIdx.x;
    __shared__ float red[256];
    __shared__ float bc[2];
    float m = -1e30f;
    for (int t = tid; t < Tz; t += 256) m = fmaxf(m, gScores[b * Tz + t]);
    red[tid] = m;
    __syncthreads();
    for (int s = 128; s > 0; s >>= 1) {
        if (tid < s) red[tid] = fmaxf(red[tid], red[tid + s]);
        __syncthreads();
    }
    if (tid == 0) bc[0] = red[0];
    __syncthreads();
    m = bc[0];
    float s = 0.f;
    for (int t = tid; t < Tz; t += 256)
        s += expf(gScores[b * Tz + t] - m) * mask[b * Tz + t];
    red[tid] = s;
    __syncthreads();
    for (int s2 = 128; s2 > 0; s2 >>= 1) {
        if (tid < s2) red[tid] += red[tid + s2];
        __syncthreads();
    }
    if (tid == 0) bc[1] = red[0];
    __syncthreads();
    float inv = 1.f / bc[1];
    for (int t = tid; t < Tz; t += 256) {
        float pm = expf(gScores[b * Tz + t] - m) * mask[b * Tz + t];
        gAttn[b * Tz + t] = pm * inv + stmt[b * Tz + t] * mask[b * Tz + t];
    }
}

// context partials: grid (64, 4), 512 threads
__global__ void k_ctx(const float* __restrict__ enc) {
    int b = blockIdx.x, ch = blockIdx.y, n = threadIdx.x;
    int t0 = ch * 100;
    float acc = 0.f;
#pragma unroll 4
    for (int t = 0; t < 100; t++) {
        float a = gAttn[b * Tz + t0 + t];
        acc += a * enc[((size_t)b * Tz + t0 + t) * 512 + n];
    }
    gCtPart[ch][b * 512 + n] = acc;
}

// reduce context partials + p_gen. grid 64, 512 threads
__global__ void k_pgen(const float* __restrict__ Wpg, const float* __restrict__ bpg,
                       const float* __restrict__ bxc) {
    int b = blockIdx.x, n = threadIdx.x;
    __shared__ float red[512];
    float ct = gCtPart[0][b * 512 + n] + gCtPart[1][b * 512 + n]
             + gCtPart[2][b * 512 + n] + gCtPart[3][b * 512 + n];
    gCt[b * 512 + n] = ct;
    float p = Wpg[n] * ct;
    if (n < 256) p += Wpg[512 + n] * gHs[b * 256 + n] + Wpg[768 + n] * gCs[b * 256 + n];
    if (n < 128) {
        float xv = bxc[n];
#pragma unroll
        for (int pp = 0; pp < 5; pp++) xv += gXPart[pp][b * 128 + n];
        p += Wpg[1024 + n] * xv;
    }
    red[n] = p;
    __syncthreads();
    for (int s = 256; s > 0; s >>= 1) {
        if (n < s) red[n] += red[n + s];
        __syncthreads();
    }
    if (n == 0) gPgen[b] = 1.f / (1.f + expf(-(red[0] + bpg[0])));
}

// ---------------- vocab GEMM: 128 v x 64 b per block, f32x2 FMA ----------------
#define LOG_NV 128
#define LOG_KT 32
__global__ void __launch_bounds__(128) k_logits(const float* __restrict__ Wo2,
                                                const float* __restrict__ bo2,
                                                const float* __restrict__ bo1) {
    __shared__ float sA[LOG_KT * 64];        // [k][b]
    __shared__ float sW[LOG_KT * LOG_NV];    // [k][v ^ ((k>>2)*4)]
    int tid = threadIdx.x;
    int tx = tid & 7;
    int ty = tid >> 3;
    int v0 = ty * 8;
    int vb = blockIdx.x * LOG_NV;

    unsigned long long acc[4][8];
#pragma unroll
    for (int p = 0; p < 4; p++)
#pragma unroll
        for (int j = 0; j < 8; j++) acc[p][j] = 0ULL;

    for (int k0 = 0; k0 < 256; k0 += LOG_KT) {
        __syncthreads();
        // A tile: sum 6 out1^T partials + bo1
#pragma unroll
        for (int r = 0; r < 4; r++) {
            int fid = r * 128 + tid;
            int k = fid >> 4, bq = fid & 15;
            float bb = bo1[k0 + k];
            float4 v = make_float4(bb, bb, bb, bb);
#pragma unroll
            for (int p = 0; p < 6; p++) {
                float4 t = *(const float4*)&gO1TPart[p][(k0 + k) * 64 + bq * 4];
                v.x += t.x; v.y += t.y; v.z += t.z; v.w += t.w;
            }
            *(float4*)&sA[k * 64 + bq * 4] = v;
        }
        // W tile: XOR-swizzled
#pragma unroll
        for (int r = 0; r < 8; r++) {
            int fid = r * 128 + tid;
            int v = fid >> 3, kq = fid & 7;
            int vg = vb + v;
            float4 w = (vg < Vz) ? *(const float4*)&Wo2[(size_t)vg * 256 + k0 + kq * 4]
                                 : make_float4(0.f, 0.f, 0.f, 0.f);
            int sv = v ^ (kq * 4);
            sW[(kq * 4 + 0) * LOG_NV + sv] = w.x;
            sW[(kq * 4 + 1) * LOG_NV + sv] = w.y;
            sW[(kq * 4 + 2) * LOG_NV + sv] = w.z;
            sW[(kq * 4 + 3) * LOG_NV + sv] = w.w;
        }
        __syncthreads();
#pragma unroll
        for (int k = 0; k < LOG_KT; k++) {
            float4 aA = *(const float4*)&sA[k * 64 + tx * 4];
            float4 aB = *(const float4*)&sA[k * 64 + 32 + tx * 4];
            int s = (k >> 2) * 4;
            const float* wr = &sW[k * LOG_NV];
            float4 w0 = *(const float4*)&wr[v0 ^ s];
            float4 w1 = *(const float4*)&wr[(v0 + 4) ^ s];
            unsigned long long ap0 = pack2(aA.x, aA.y);
            unsigned long long ap1 = pack2(aA.z, aA.w);
            unsigned long long ap2 = pack2(aB.x, aB.y);
            unsigned long long ap3 = pack2(aB.z, aB.w);
            float wv[8] = {w0.x, w0.y, w0.z, w0.w, w1.x, w1.y, w1.z, w1.w};
#pragma unroll
            for (int j = 0; j < 8; j++) {
                unsigned long long wd = pack2(wv[j], wv[j]);
                fma2(acc[0][j], ap0, wd);
                fma2(acc[1][j], ap1, wd);
                fma2(acc[2][j], ap2, wd);
                fma2(acc[3][j], ap3, wd);
            }
        }
    }
    int vg0 = vb + v0;
    if (vg0 + 7 < Vz) {
        float4 bi0 = *(const float4*)&bo2[vg0];
        float4 bi1 = *(const float4*)&bo2[vg0 + 4];
#pragma unroll
        for (int p = 0; p < 4; p++) {
            float2 u0 = unpk2(acc[p][0]), u1 = unpk2(acc[p][1]);
            float2 u2 = unpk2(acc[p][2]), u3 = unpk2(acc[p][3]);
            float2 u4 = unpk2(acc[p][4]), u5 = unpk2(acc[p][5]);
            float2 u6 = unpk2(acc[p][6]), u7 = unpk2(acc[p][7]);
            int bLo = (p >> 1) * 32 + tx * 4 + (p & 1) * 2;
            float4 lo0 = make_float4(u0.x + bi0.x, u1.x + bi0.y, u2.x + bi0.z, u3.x + bi0.w);
            float4 lo1 = make_float4(u4.x + bi1.x, u5.x + bi1.y, u6.x + bi1.z, u7.x + bi1.w);
            float4 hi0 = make_float4(u0.y + bi0.x, u1.y + bi0.y, u2.y + bi0.z, u3.y + bi0.w);
            float4 hi1 = make_float4(u4.y + bi1.x, u5.y + bi1.y, u6.y + bi1.z, u7.y + bi1.w);
            *(float4*)&gLogits[(size_t)bLo * Vz + vg0] = lo0;
            *(float4*)&gLogits[(size_t)bLo * Vz + vg0 + 4] = lo1;
            *(float4*)&gLogits[(size_t)(bLo + 1) * Vz + vg0] = hi0;
            *(float4*)&gLogits[(size_t)(bLo + 1) * Vz + vg0 + 4] = hi1;
        }
    }
}

// per-row max & sum(exp) over V. grid 64, 512 threads
__global__ void k_rowred() {
    int b = blockIdx.x, tid = threadIdx.x;
    __shared__ float red[512];
    __shared__ float bm;
    const float4* row = (const float4*)(gLogits + (size_t)b * Vz);
    float m = -1e30f;
    for (int v = tid; v < Vz / 4; v += 512) {
        float4 x = row[v];
        m = fmaxf(m, fmaxf(fmaxf(x.x, x.y), fmaxf(x.z, x.w)));
    }
    red[tid] = m;
    __syncthreads();
    for (int s = 256; s > 0; s >>= 1) {
        if (tid < s) red[tid] = fmaxf(red[tid], red[tid + s]);
        __syncthreads();
    }
    if (tid == 0) bm = red[0];
    __syncthreads();
    float mm = bm;
    float s = 0.f;
    for (int v = tid; v < Vz / 4; v += 512) {
        float4 x = row[v];
        s += expf(x.x - mm) + expf(x.y - mm) + expf(x.z - mm) + expf(x.w - mm);
    }
    red[tid] = s;
    __syncthreads();
    for (int s2 = 256; s2 > 0; s2 >>= 1) {
        if (tid < s2) red[tid] += red[tid + s2];
        __syncthreads();
    }
    if (tid == 0) {
        gRowMax[b] = mm;
        gScale[b] = gPgen[b] / red[0];
    }
}

// final_dist (float4) + extra_zeros + pack small outputs
__global__ void k_final(float* __restrict__ out, const float* __restrict__ coverage,
                        int writeAll) {
    const int ROW4 = VXz / 4;
    long long idx = (long long)blockIdx.x * 256 + threadIdx.x;
    const long long MAIN4 = (long long)Bz * ROW4;
    if (idx < MAIN4) {
        int b = (int)(idx / ROW4);
        int v = (int)(idx - (long long)b * ROW4) * 4;
        float4 r = make_float4(0.f, 0.f, 0.f, 0.f);
        if (v < Vz) {
            float m = gRowMax[b], sc = gScale[b];
            float4 lg = *(const float4*)&gLogits[(size_t)b * Vz + v];
            r.x = expf(lg.x - m) * sc;
            r.y = expf(lg.y - m) * sc;
            r.z = expf(lg.z - m) * sc;
            r.w = expf(lg.w - m) * sc;
        }
        *(float4*)&out[(size_t)b * VXz + v] = r;
    } else if (writeAll) {
        long long j = idx - MAIN4;
        float r;
        long long base = (long long)Bz * VXz;
        if (j < 16384) r = gHs[j];
        else if ((j -= 16384) < 16384) r = gCs[j];
        else if ((j -= 16384) < 32768) r = gCt[j];
        else if ((j -= 32768) < 25600) r = gAttn[j];
        else if ((j -= 25600) < 64) r = gPgen[j];
        else if ((j -= 64) < 25600) r = coverage[j];
        else return;
        out[base + (idx - MAIN4)] = r;
    }
}

// scatter-add attention distribution into final_dist
__global__ void k_scatter(float* __restrict__ out, const int* __restrict__ ebev) {
    int i = blockIdx.x * 256 + threadIdx.x;
    if (i >= Bz * Tz) return;
    int b = i / Tz;
    float val = (1.f - gPgen[b]) * gAttn[i];
    atomicAdd(&out[(size_t)b * VXz + ebev[i]], val);
}

// ---------------- launcher ----------------
extern "C" void kernel_launch(void* const* d_in, const int* in_sizes, int n_in,
                              void* d_out, int out_size) {
    const int*   y    = (const int*)d_in[0];
    const float* h0   = (const float*)d_in[1];
    const float* c0   = (const float*)d_in[2];
    const float* enc  = (const float*)d_in[3];
    const float* ef   = (const float*)d_in[4];
    const float* stmt = (const float*)d_in[5];
    const float* mask = (const float*)d_in[6];
    const float* ct1  = (const float*)d_in[7];
    const int*   ebev = (const int*)d_in[9];
    const float* cov  = (const float*)d_in[10];
    int base = (n_in >= 28) ? 12 : 11;
    const float* emb  = (const float*)d_in[base + 0];
    const float* Wxc  = (const float*)d_in[base + 1];
    const float* bxc  = (const float*)d_in[base + 2];
    const float* W_ih = (const float*)d_in[base + 3];
    const float* W_hh = (const float*)d_in[base + 4];
    const float* b_ih = (const float*)d_in[base + 5];
    const float* b_hh = (const float*)d_in[base + 6];
    const float* Wdp  = (const float*)d_in[base + 7];
    const float* bdp  = (const float*)d_in[base + 8];
    const float* Wv   = (const float*)d_in[base + 9];
    const float* Wpg  = (const float*)d_in[base + 10];
    const float* bpg  = (const float*)d_in[base + 11];
    const float* Wo1  = (const float*)d_in[base + 12];
    const float* bo1  = (const float*)d_in[base + 13];
    const float* Wo2  = (const float*)d_in[base + 14];
    const float* bo2  = (const float*)d_in[base + 15];
    float* out = (float*)d_out;

    float* pXP;  cudaGetSymbolAddress((void**)&pXP, gXPart);
    float* pGP;  cudaGetSymbolAddress((void**)&pGP, gGatesPart);
    float* pDP;  cudaGetSymbolAddress((void**)&pDP, gDecPart);
    float* pO1T; cudaGetSymbolAddress((void**)&pO1T, gO1TPart);
    float* pHs;  cudaGetSymbolAddress((void**)&pHs, gHs);
    float* pCs;  cudaGetSymbolAddress((void**)&pCs, gCs);
    float* pCt;  cudaGetSymbolAddress((void**)&pCt, gCt);

    // 1) x partials: [c_t_1, emb[y]] @ Wxc^T  (KD=640, N=128) grid (8,5)
    k_gemm<<<dim3(8, 5), 256>>>(ct1, 512, 1, 0, nullptr,
                                emb, 128, y,
                                Wxc, 640, Wxc + 512, 640,
                                pXP, nullptr, 128);
    // 2) gate partials: [x, h0] @ [W_ih|W_hh]^T  (KD=384, N=1024) grid (64,3)
    k_gemm<<<dim3(64, 3), 256>>>(pXP, 128, 5, Bz * Ez, bxc,
                                 h0, 256, nullptr,
                                 W_ih, 128, W_hh, 256,
                                 pGP, nullptr, 1024);
    // 3) LSTM nonlinearity (sums partials + biases)
    k_lstm<<<Bz, 256>>>(c0, b_ih, b_hh);
    // 4) dec_fea partials: [h_s, c_s] @ Wdp^T  (KD=512, N=512) grid (32,4)
    k_gemm<<<dim3(32, 4), 256>>>(pHs, 256, 1, 0, nullptr,
                                 pCs, 256, nullptr,
                                 Wdp, 512, Wdp + 256, 512,
                                 pDP, nullptr, 512);
    // 5) attention scores (dec partial-sum in smem)
    k_scores<<<Bz * 50, 256>>>(ef, Wv, bdp);
    // 6) softmax over T
    k_softmaxT<<<Bz, 256>>>(mask, stmt);
    // 7) context partials
    k_ctx<<<dim3(Bz, 4), 512>>>(enc);
    // 8) context reduce + p_gen (+x reduce)
    k_pgen<<<Bz, 512>>>(Wpg, bpg, bxc);
    // 9) out1^T partials: [h_s, c_t] @ Wo1^T  (KD=768, N=256) grid (16,6)
    k_gemm<<<dim3(16, 6), 256>>>(pHs, 256, 1, 0, nullptr,
                                 pCt, 512, nullptr,
                                 Wo1, 768, Wo1 + 256, 768,
                                 nullptr, pO1T, 256);
    // 10) vocab logits GEMM (f32x2, A = sum of out1^T partials + bo1)
    k_logits<<<(Vz + LOG_NV - 1) / LOG_NV, 128>>>(Wo2, bo2, bo1);
    // 11) row max + sum(exp)
    k_rowred<<<Bz, 512>>>();
    // 12) final dist + pack
    const long long MAIN4 = (long long)Bz * (VXz / 4);
    const long long TAIL  = 16384 + 16384 + 32768 + 25600 + 64 + 25600;
    const long long ALL   = (long long)Bz * VXz + TAIL;
    int writeAll = ((long long)out_size >= ALL) ? 1 : 0;
    long long slots = MAIN4 + (writeAll ? TAIL : 0);
    k_final<<<(unsigned)((slots + 255) / 256), 256>>>(out, cov, writeAll);
    // 13) scatter-add
    k_scatter<<<(Bz * Tz + 255) / 256, 256>>>(out, ebev);
}